// round 15
// baseline (speedup 1.0000x reference)
#include <cuda_runtime.h>
#include <cuda_fp16.h>
#include <cstdint>
#include <math.h>

// Problem dims (fixed by setup_inputs)
#define Bb 8
#define Ss 4096
#define Dd 512
#define Hh 512
#define GH 1024
#define Mm (Bb * Ss)          // 32768 rows
#define KA 512                // A operand K (plain fp16)
#define KB 512                // B operand K (plain fp16)
#define KP 512                // GEMM K'
#define NCHUNK 64
#define CLEN (Ss / NCHUNK)    // 64
#define NCH (Bb * Hh)

// Scratch (device globals: allocation-free per harness rules)
__device__ __half g_gh[(size_t)Mm * GH];    // (c,v) half2 pairs after GEMM+act
__device__ __half g_Ax[(size_t)Mm * KA];    // layer-0 A operand (fp16)
__device__ __half g_A1[(size_t)Mm * KA];    // layer-1 A operand (fp16 h)
__device__ __half g_Wb0[(size_t)GH * KB];   // fp16 weights, rows channel-interleaved
__device__ __half g_Wb1[(size_t)GH * KB];
__device__ float g_carryP[NCHUNK * NCH];
__device__ float g_carryH[NCHUNK * NCH];
__device__ float g_entry[NCHUNK * NCH];

// ===========================================================================
// Helpers
// ===========================================================================
__device__ __forceinline__ uint32_t smem_u32(const void* p) {
    uint32_t a;
    asm("{ .reg .u64 t; cvta.to.shared.u64 t, %1; cvt.u32.u64 %0, t; }" : "=r"(a) : "l"(p));
    return a;
}

#define CP_ASYNC16(smaddr, gptr) \
    asm volatile("cp.async.cg.shared.global [%0], [%1], 16;" :: "r"(smaddr), "l"(gptr) : "memory")
#define CP_COMMIT  asm volatile("cp.async.commit_group;" ::: "memory")
#define CP_WAIT0   asm volatile("cp.async.wait_group 0;" ::: "memory")

#define LDSM_X4(r0, r1, r2, r3, addr) \
    asm volatile("ldmatrix.sync.aligned.m8n8.x4.shared.b16 {%0,%1,%2,%3}, [%4];" \
        : "=r"(r0), "=r"(r1), "=r"(r2), "=r"(r3) : "r"(addr))

#define MMA16816(c, a, b) \
    asm volatile("mma.sync.aligned.m16n8k16.row.col.f32.f16.f16.f32 " \
        "{%0,%1,%2,%3}, {%4,%5,%6,%7}, {%8,%9}, {%0,%1,%2,%3};" \
        : "+f"((c)[0]), "+f"((c)[1]), "+f"((c)[2]), "+f"((c)[3]) \
        : "r"((a)[0]), "r"((a)[1]), "r"((a)[2]), "r"((a)[3]), "r"((b)[0]), "r"((b)[1]))

// Fused activation: from (gate, hidden) produce (c, v)
//   c = sigmoid(-gate), v = sigmoid(gate) * g(hidden)
__device__ __forceinline__ float2 act_pair(float gate, float hid) {
    float e = __expf(-gate);
    float z = __fdividef(1.0f, 1.0f + e);    // sigmoid(gate)
    float cc = e * z;                         // sigmoid(-gate)
    float gg = (hid >= 0.0f) ? (hid + 0.5f)
                             : __fdividef(1.0f, 1.0f + __expf(-hid));
    float2 r; r.x = cc; r.y = z * gg;
    return r;
}

// ===========================================================================
// Conversion kernels
// ===========================================================================
// A: fp32 [rows][512] -> plain fp16 [rows][512]
__global__ __launch_bounds__(256) void conv_a_kernel(
    const float* __restrict__ in, __half* __restrict__ out)
{
    const int g = blockIdx.x * 256 + threadIdx.x;
    const int row = g >> 7;
    const int k4 = (g & 127) * 4;
    float4 f = *(const float4*)(in + (size_t)row * KA + k4);
    __half2 p0 = __floats2half2_rn(f.x, f.y);
    __half2 p1 = __floats2half2_rn(f.z, f.w);
    uint2 v = make_uint2(*reinterpret_cast<uint32_t*>(&p0), *reinterpret_cast<uint32_t*>(&p1));
    *(uint2*)(out + (size_t)row * KA + k4) = v;
}

// B: fp32 [1024][512] -> fp16 [1024][512] with output-channel interleave:
// source row n -> dest row (2n) for n<512 (gate), (2(n-512)+1) for n>=512.
__global__ __launch_bounds__(256) void conv_b_kernel(
    const float* __restrict__ in, __half* __restrict__ out)
{
    const int g = blockIdx.x * 256 + threadIdx.x;
    const int row = g >> 7;
    const int prow = (row < 512) ? (row * 2) : ((row - 512) * 2 + 1);
    const int k4 = (g & 127) * 4;
    float4 f = *(const float4*)(in + (size_t)row * KA + k4);
    __half2 p0 = __floats2half2_rn(f.x, f.y);
    __half2 p1 = __floats2half2_rn(f.z, f.w);
    uint2 v = make_uint2(*reinterpret_cast<uint32_t*>(&p0), *reinterpret_cast<uint32_t*>(&p1));
    *(uint2*)(out + (size_t)prow * KB + k4) = v;
}

// ===========================================================================
// HMMA GEMM + fused activation, fp16 (c,v) output.
// A: [Mm][512] fp16, B: [GH][512] fp16 channel-interleaved rows.
// CTA tile 128x256, 8 warps as 2(M) x 4(N), warp tile 64x64 (4 mf x 8 nf).
// BK=64, 2-stage cp.async, one sync/K-tile, single-buffered fragments.
// ===========================================================================
#define BM 128
#define BN 256
#define BK 64
#define NKT (KP / BK)          // 8
#define STG_A 16384            // 128 rows x 128B
#define STG_B 32768            // 256 rows x 128B
#define GEMM_SMEM (2 * (STG_A + STG_B))   // 98304

__global__ __launch_bounds__(256, 1) void hmma_gemm_act(
    const __half* __restrict__ A, const __half* __restrict__ Bw,
    const float* __restrict__ bias, __half2* __restrict__ C2)
{
    extern __shared__ char sm[];
    const uint32_t sA = smem_u32(sm);          // [2][16384]
    const uint32_t sB = sA + 2 * STG_A;        // [2][32768]
    const int tid = threadIdx.x;
    const int lane = tid & 31;
    const int wid = tid >> 5;
    const int rowBase = blockIdx.y * BM;
    const int colBase = blockIdx.x * BN;
    const int wm = (wid & 1) * 64;             // warp M offset (2 warps in M)
    const int wn = (wid >> 1) * 64;            // warp N offset (4 warps in N)

    float acc[4][8][4];
#pragma unroll
    for (int mf = 0; mf < 4; mf++)
#pragma unroll
        for (int nf = 0; nf < 8; nf++)
#pragma unroll
            for (int j = 0; j < 4; j++) acc[mf][nf][j] = 0.f;

    auto loadStage = [&](int kt, int s) {
        // A: 128 rows x 128B = 1024 16B-chunks
#pragma unroll
        for (int i = 0; i < 4; i++) {
            const int id = tid + i * 256;
            const int r = id >> 3, c = id & 7;
            uint32_t off = (uint32_t)(r * 128 + c * 16);
            off ^= (off >> 3) & 0x70;
            CP_ASYNC16(sA + s * STG_A + off,
                       A + (size_t)(rowBase + r) * KA + kt * BK + c * 8);
        }
        // B: 256 rows x 128B = 2048 16B-chunks
#pragma unroll
        for (int i = 0; i < 8; i++) {
            const int id = tid + i * 256;
            const int r = id >> 3, c = id & 7;
            uint32_t off = (uint32_t)(r * 128 + c * 16);
            off ^= (off >> 3) & 0x70;
            CP_ASYNC16(sB + s * STG_B + off,
                       Bw + (size_t)(colBase + r) * KB + kt * BK + c * 8);
        }
        CP_COMMIT;
    };

    loadStage(0, 0);

    for (int kt = 0; kt < NKT; kt++) {
        const int s = kt & 1;
        CP_WAIT0;            // stage kt resident
        __syncthreads();     // all warps done reading the other buffer
        if (kt + 1 < NKT) loadStage(kt + 1, s ^ 1);   // prefetch, overlapped

        const uint32_t aB = sA + s * STG_A;
        const uint32_t bB = sB + s * STG_B;
#pragma unroll
        for (int ks = 0; ks < 4; ks++) {
            uint32_t af[4][4];
#pragma unroll
            for (int mf = 0; mf < 4; mf++) {
                const int r = wm + mf * 16 + (lane & 15);
                const int kb = ks * 32 + (lane >> 4) * 16;
                uint32_t off = (uint32_t)(r * 128 + kb);
                off ^= (off >> 3) & 0x70;
                LDSM_X4(af[mf][0], af[mf][1], af[mf][2], af[mf][3], aB + off);
            }
            uint32_t bf[8][2];
#pragma unroll
            for (int n2 = 0; n2 < 4; n2++) {
                const int r = wn + n2 * 16 + (lane & 7) + ((lane >> 4) & 1) * 8;
                const int kb = ks * 32 + ((lane >> 3) & 1) * 16;
                uint32_t off = (uint32_t)(r * 128 + kb);
                off ^= (off >> 3) & 0x70;
                LDSM_X4(bf[2 * n2][0], bf[2 * n2][1],
                        bf[2 * n2 + 1][0], bf[2 * n2 + 1][1], bB + off);
            }
#pragma unroll
            for (int mf = 0; mf < 4; mf++)
#pragma unroll
                for (int nf = 0; nf < 8; nf++)
                    MMA16816(acc[mf][nf], af[mf], bf[nf]);
        }
    }

    // Epilogue: each float2 pair = (gate, hidden) of channel h -> store half2 (c, v)
#pragma unroll
    for (int nf = 0; nf < 8; nf++) {
        const int col = colBase + wn + nf * 8 + 2 * (lane & 3);   // even
        const int h = col >> 1;
        const float bg = __ldg(bias + h);
        const float bh = __ldg(bias + 512 + h);
#pragma unroll
        for (int mf = 0; mf < 4; mf++) {
            const int r0 = rowBase + wm + mf * 16 + (lane >> 2);
            float2 p0 = act_pair(acc[mf][nf][0] + bg, acc[mf][nf][1] + bh);
            float2 p1 = act_pair(acc[mf][nf][2] + bg, acc[mf][nf][3] + bh);
            C2[(size_t)r0 * Hh + h] = __floats2half2_rn(p0.x, p0.y);
            C2[(size_t)(r0 + 8) * Hh + h] = __floats2half2_rn(p1.x, p1.y);
        }
    }
}

// ===========================================================================
// Scan over half2 (c, v) pairs: h_t = c_t * h_{t-1} + v_t   (fp32 state)
// ===========================================================================
__global__ __launch_bounds__(256) void scan_carry1_kernel(const __half2* __restrict__ gh)
{
    const int g = blockIdx.x * blockDim.x + threadIdx.x;
    const int h = g & (Hh - 1);
    const int rest = g >> 9;
    const int b = rest & (Bb - 1);
    const int k = rest >> 3;

    const __half2* p = gh + ((size_t)(b * Ss + k * CLEN) * Hh + h);
    float P = 1.0f, hl = 0.0f;
#pragma unroll 8
    for (int i = 0; i < CLEN; i++) {
        float2 cv = __half22float2(*p);
        hl = fmaf(cv.x, hl, cv.y);
        P *= cv.x;
        p += Hh;
    }
    const int ch = b * Hh + h;
    g_carryP[k * NCH + ch] = P;
    g_carryH[k * NCH + ch] = hl;
}

__global__ __launch_bounds__(256) void scan_carry_kernel(float* __restrict__ nh_out)
{
    const int ch = blockIdx.x * blockDim.x + threadIdx.x;
    float hcur = 0.5f;
#pragma unroll 4
    for (int k = 0; k < NCHUNK; k++) {
        g_entry[k * NCH + ch] = hcur;
        hcur = fmaf(g_carryP[k * NCH + ch], hcur, g_carryH[k * NCH + ch]);
    }
    nh_out[ch] = hcur;
}

// Pass 3, layer-1: write final fp32 output
__global__ __launch_bounds__(256) void scan_emit_f32_kernel(
    const __half2* __restrict__ gh, float* __restrict__ outbuf)
{
    const int g = blockIdx.x * blockDim.x + threadIdx.x;
    const int h = g & (Hh - 1);
    const int rest = g >> 9;
    const int b = rest & (Bb - 1);
    const int k = rest >> 3;

    float hv = g_entry[k * NCH + b * Hh + h];
    const __half2* p = gh + ((size_t)(b * Ss + k * CLEN) * Hh + h);
    size_t obase = ((size_t)(b * Ss + k * CLEN)) * Hh + h;
#pragma unroll 8
    for (int i = 0; i < CLEN; i++) {
        float2 cv = __half22float2(*p);
        hv = fmaf(cv.x, hv, cv.y);
        outbuf[obase] = hv;
        p += Hh;
        obase += Hh;
    }
}

// Pass 3, layer-0: write fp16 A operand for layer 1
__global__ __launch_bounds__(256) void scan_emit_f16_kernel(
    const __half2* __restrict__ gh, __half* __restrict__ outA)
{
    const int g = blockIdx.x * blockDim.x + threadIdx.x;
    const int h = g & (Hh - 1);
    const int rest = g >> 9;
    const int b = rest & (Bb - 1);
    const int k = rest >> 3;

    float hv = g_entry[k * NCH + b * Hh + h];
    const __half2* p = gh + ((size_t)(b * Ss + k * CLEN) * Hh + h);
    size_t obase = ((size_t)(b * Ss + k * CLEN)) * Hh + h;
#pragma unroll 8
    for (int i = 0; i < CLEN; i++) {
        float2 cv = __half22float2(*p);
        hv = fmaf(cv.x, hv, cv.y);
        outA[obase] = __float2half_rn(hv);
        p += Hh;
        obase += Hh;
    }
}

// ===========================================================================
extern "C" void kernel_launch(void* const* d_in, const int* in_sizes, int n_in,
                              void* d_out, int out_size)
{
    const float* x  = (const float*)d_in[0];
    const float* w0 = (const float*)d_in[1];
    const float* b0 = (const float*)d_in[2];
    const float* w1 = (const float*)d_in[3];
    const float* b1 = (const float*)d_in[4];
    float* out = (float*)d_out;

    __half* gh;  cudaGetSymbolAddress((void**)&gh,  g_gh);
    __half* Ax;  cudaGetSymbolAddress((void**)&Ax,  g_Ax);
    __half* A1;  cudaGetSymbolAddress((void**)&A1,  g_A1);
    __half* Wb0; cudaGetSymbolAddress((void**)&Wb0, g_Wb0);
    __half* Wb1; cudaGetSymbolAddress((void**)&Wb1, g_Wb1);

    float* nh0 = out + (size_t)Mm * Hh;
    float* nh1 = nh0 + (size_t)Bb * Hh;

    cudaFuncSetAttribute(hmma_gemm_act,
                         cudaFuncAttributeMaxDynamicSharedMemorySize, GEMM_SMEM);

    dim3 ggrid(GH / BN, Mm / BM);                  // (4, 256)
    const int scan_blocks = (NCHUNK * NCH) / 256;  // 1024

    // One-time conversions (cheap)
    conv_b_kernel<<<(GH * 128) / 256, 256>>>(w0, Wb0);
    conv_b_kernel<<<(GH * 128) / 256, 256>>>(w1, Wb1);
    conv_a_kernel<<<(Mm * 128) / 256, 256>>>(x, Ax);

    // ---- Layer 0 ----
    hmma_gemm_act<<<ggrid, 256, GEMM_SMEM>>>(Ax, Wb0, b0, (__half2*)gh);
    scan_carry1_kernel<<<scan_blocks, 256>>>((const __half2*)gh);
    scan_carry_kernel<<<NCH / 256, 256>>>(nh0);
    scan_emit_f16_kernel<<<scan_blocks, 256>>>((const __half2*)gh, A1);

    // ---- Layer 1 ----
    hmma_gemm_act<<<ggrid, 256, GEMM_SMEM>>>(A1, Wb1, b1, (__half2*)gh);
    scan_carry1_kernel<<<scan_blocks, 256>>>((const __half2*)gh);
    scan_carry_kernel<<<NCH / 256, 256>>>(nh1);
    scan_emit_f32_kernel<<<scan_blocks, 256>>>((const __half2*)gh, out);
}

// round 16
// speedup vs baseline: 1.0683x; 1.0683x over previous
#include <cuda_runtime.h>
#include <cuda_fp16.h>
#include <cstdint>
#include <math.h>

// Problem dims (fixed by setup_inputs)
#define Bb 8
#define Ss 4096
#define Dd 512
#define Hh 512
#define GH 1024
#define Mm (Bb * Ss)          // 32768 rows
#define KA 512                // A operand K (plain fp16)
#define KB 512                // B operand K (plain fp16)
#define KP 512                // GEMM K'
#define NCHUNK 64
#define CLEN (Ss / NCHUNK)    // 64
#define NCH (Bb * Hh)

// Scratch (device globals: allocation-free per harness rules)
__device__ __half g_gh[(size_t)Mm * GH];    // (c,v) half2 pairs after GEMM+act
__device__ __half g_Ax[(size_t)Mm * KA];    // layer-0 A operand (fp16)
__device__ __half g_A1[(size_t)Mm * KA];    // layer-1 A operand (fp16 h)
__device__ __half g_Wb0[(size_t)GH * KB];   // fp16 weights, rows channel-interleaved
__device__ __half g_Wb1[(size_t)GH * KB];
__device__ float g_carryP[NCHUNK * NCH];
__device__ float g_carryH[NCHUNK * NCH];
__device__ float g_entry[NCHUNK * NCH];

// ===========================================================================
// Helpers
// ===========================================================================
__device__ __forceinline__ uint32_t smem_u32(const void* p) {
    uint32_t a;
    asm("{ .reg .u64 t; cvta.to.shared.u64 t, %1; cvt.u32.u64 %0, t; }" : "=r"(a) : "l"(p));
    return a;
}

#define CP_ASYNC16(smaddr, gptr) \
    asm volatile("cp.async.cg.shared.global [%0], [%1], 16;" :: "r"(smaddr), "l"(gptr) : "memory")
#define CP_COMMIT  asm volatile("cp.async.commit_group;" ::: "memory")
#define CP_WAIT0   asm volatile("cp.async.wait_group 0;" ::: "memory")

#define LDSM_X4(r0, r1, r2, r3, addr) \
    asm volatile("ldmatrix.sync.aligned.m8n8.x4.shared.b16 {%0,%1,%2,%3}, [%4];" \
        : "=r"(r0), "=r"(r1), "=r"(r2), "=r"(r3) : "r"(addr))

#define MMA16816(c, a, b) \
    asm volatile("mma.sync.aligned.m16n8k16.row.col.f32.f16.f16.f32 " \
        "{%0,%1,%2,%3}, {%4,%5,%6,%7}, {%8,%9}, {%0,%1,%2,%3};" \
        : "+f"((c)[0]), "+f"((c)[1]), "+f"((c)[2]), "+f"((c)[3]) \
        : "r"((a)[0]), "r"((a)[1]), "r"((a)[2]), "r"((a)[3]), "r"((b)[0]), "r"((b)[1]))

// Fused activation: from (gate, hidden) produce (c, v)
//   c = sigmoid(-gate), v = sigmoid(gate) * g(hidden)
__device__ __forceinline__ float2 act_pair(float gate, float hid) {
    float e = __expf(-gate);
    float z = __fdividef(1.0f, 1.0f + e);    // sigmoid(gate)
    float cc = e * z;                         // sigmoid(-gate)
    float gg = (hid >= 0.0f) ? (hid + 0.5f)
                             : __fdividef(1.0f, 1.0f + __expf(-hid));
    float2 r; r.x = cc; r.y = z * gg;
    return r;
}

// ===========================================================================
// Conversion kernels
// ===========================================================================
// A: fp32 [rows][512] -> plain fp16 [rows][512]
__global__ __launch_bounds__(256) void conv_a_kernel(
    const float* __restrict__ in, __half* __restrict__ out)
{
    const int g = blockIdx.x * 256 + threadIdx.x;
    const int row = g >> 7;
    const int k4 = (g & 127) * 4;
    float4 f = *(const float4*)(in + (size_t)row * KA + k4);
    __half2 p0 = __floats2half2_rn(f.x, f.y);
    __half2 p1 = __floats2half2_rn(f.z, f.w);
    uint2 v = make_uint2(*reinterpret_cast<uint32_t*>(&p0), *reinterpret_cast<uint32_t*>(&p1));
    *(uint2*)(out + (size_t)row * KA + k4) = v;
}

// B: fp32 [1024][512] -> fp16 [1024][512] with output-channel interleave:
// source row n -> dest row (2n) for n<512 (gate), (2(n-512)+1) for n>=512.
__global__ __launch_bounds__(256) void conv_b_kernel(
    const float* __restrict__ in, __half* __restrict__ out)
{
    const int g = blockIdx.x * 256 + threadIdx.x;
    const int row = g >> 7;
    const int prow = (row < 512) ? (row * 2) : ((row - 512) * 2 + 1);
    const int k4 = (g & 127) * 4;
    float4 f = *(const float4*)(in + (size_t)row * KA + k4);
    __half2 p0 = __floats2half2_rn(f.x, f.y);
    __half2 p1 = __floats2half2_rn(f.z, f.w);
    uint2 v = make_uint2(*reinterpret_cast<uint32_t*>(&p0), *reinterpret_cast<uint32_t*>(&p1));
    *(uint2*)(out + (size_t)prow * KB + k4) = v;
}

// ===========================================================================
// HMMA GEMM + fused activation, fp16 (c,v) output, smem-staged coalesced
// epilogue stores.
// A: [Mm][512] fp16, B: [GH][512] fp16 channel-interleaved rows.
// CTA tile 128x128, warp tile 32x64 (4Mx2N warps), BK=64, 2-stage cp.async,
// one sync/K-tile, double-buffered register fragments. 2 CTAs/SM.
// ===========================================================================
#define BM 128
#define BN 128
#define BK 64
#define NKT (KP / BK)          // 8
#define STG 16384
#define GEMM_SMEM (2 * 2 * STG)   // 65536
#define EROWS 68               // epilogue staging row stride in words

__global__ __launch_bounds__(256, 2) void hmma_gemm_act(
    const __half* __restrict__ A, const __half* __restrict__ Bw,
    const float* __restrict__ bias, __half2* __restrict__ C2)
{
    extern __shared__ char sm[];
    const uint32_t sA = smem_u32(sm);          // [2][16384]
    const uint32_t sB = sA + 2 * STG;          // [2][16384]
    const int tid = threadIdx.x;
    const int lane = tid & 31;
    const int wid = tid >> 5;
    const int rowBase = blockIdx.y * BM;
    const int colBase = blockIdx.x * BN;
    const int wm = (wid & 3) * 32;
    const int wn = (wid >> 2) * 64;

    float acc[2][8][4];
#pragma unroll
    for (int mf = 0; mf < 2; mf++)
#pragma unroll
        for (int nf = 0; nf < 8; nf++)
#pragma unroll
            for (int j = 0; j < 4; j++) acc[mf][nf][j] = 0.f;

    auto loadStage = [&](int kt, int s) {
#pragma unroll
        for (int i = 0; i < 4; i++) {
            const int id = tid + i * 256;
            const int r = id >> 3, c = id & 7;
            uint32_t off = (uint32_t)(r * 128 + c * 16);
            off ^= (off >> 3) & 0x70;
            CP_ASYNC16(sA + s * STG + off,
                       A + (size_t)(rowBase + r) * KA + kt * BK + c * 8);
        }
#pragma unroll
        for (int i = 0; i < 4; i++) {
            const int id = tid + i * 256;
            const int r = id >> 3, c = id & 7;
            uint32_t off = (uint32_t)(r * 128 + c * 16);
            off ^= (off >> 3) & 0x70;
            CP_ASYNC16(sB + s * STG + off,
                       Bw + (size_t)(colBase + r) * KB + kt * BK + c * 8);
        }
        CP_COMMIT;
    };

    // Double-buffered register fragments
    uint32_t af[2][2][4];
    uint32_t bf[2][8][2];

    auto loadFrags = [&](uint32_t aB, uint32_t bB, int ks, int pb) {
#pragma unroll
        for (int mf = 0; mf < 2; mf++) {
            const int r = wm + mf * 16 + (lane & 15);
            const int kb = ks * 32 + (lane >> 4) * 16;
            uint32_t off = (uint32_t)(r * 128 + kb);
            off ^= (off >> 3) & 0x70;
            LDSM_X4(af[pb][mf][0], af[pb][mf][1], af[pb][mf][2], af[pb][mf][3], aB + off);
        }
#pragma unroll
        for (int n2 = 0; n2 < 4; n2++) {
            const int r = wn + n2 * 16 + (lane & 7) + ((lane >> 4) & 1) * 8;
            const int kb = ks * 32 + ((lane >> 3) & 1) * 16;
            uint32_t off = (uint32_t)(r * 128 + kb);
            off ^= (off >> 3) & 0x70;
            LDSM_X4(bf[pb][2 * n2][0], bf[pb][2 * n2][1],
                    bf[pb][2 * n2 + 1][0], bf[pb][2 * n2 + 1][1], bB + off);
        }
    };

    loadStage(0, 0);

    for (int kt = 0; kt < NKT; kt++) {
        const int s = kt & 1;
        CP_WAIT0;            // stage kt resident (its load was issued last iter)
        __syncthreads();     // all warps done reading buffer s^1 (tile kt-1)
        if (kt + 1 < NKT) loadStage(kt + 1, s ^ 1);   // prefetch, overlapped

        const uint32_t aB = sA + s * STG;
        const uint32_t bB = sB + s * STG;
        loadFrags(aB, bB, 0, 0);
#pragma unroll
        for (int ks = 0; ks < 4; ks++) {
            const int cur = ks & 1;
            if (ks < 3) loadFrags(aB, bB, ks + 1, cur ^ 1);
#pragma unroll
            for (int mf = 0; mf < 2; mf++)
#pragma unroll
                for (int nf = 0; nf < 8; nf++)
                    MMA16816(acc[mf][nf], af[cur][mf], bf[cur][nf]);
        }
    }

    // ---- Epilogue phase A: activation -> smem staging (conflict-free) ----
    __syncthreads();                 // mainloop smem reads complete
    const uint32_t se = sA;          // staging: 128 rows x 64 half2, stride EROWS
#pragma unroll
    for (int nf = 0; nf < 8; nf++) {
        const int hloc = (wn >> 1) + nf * 4 + (lane & 3);   // 0..63
        const int h = (colBase >> 1) + hloc;
        const float bg = __ldg(bias + h);
        const float bh = __ldg(bias + 512 + h);
#pragma unroll
        for (int mf = 0; mf < 2; mf++) {
            const int rloc = wm + mf * 16 + (lane >> 2);
            float2 p0 = act_pair(acc[mf][nf][0] + bg, acc[mf][nf][1] + bh);
            float2 p1 = act_pair(acc[mf][nf][2] + bg, acc[mf][nf][3] + bh);
            __half2 q0 = __floats2half2_rn(p0.x, p0.y);
            __half2 q1 = __floats2half2_rn(p1.x, p1.y);
            uint32_t q0u = *reinterpret_cast<uint32_t*>(&q0);
            uint32_t q1u = *reinterpret_cast<uint32_t*>(&q1);
            asm volatile("st.shared.b32 [%0], %1;"
                :: "r"(se + (uint32_t)((rloc * EROWS + hloc) << 2)), "r"(q0u) : "memory");
            asm volatile("st.shared.b32 [%0], %1;"
                :: "r"(se + (uint32_t)(((rloc + 8) * EROWS + hloc) << 2)), "r"(q1u) : "memory");
        }
    }
    __syncthreads();

    // ---- Epilogue phase B: 16B coalesced stores to gmem ----
#pragma unroll
    for (int i = 0; i < 8; i++) {
        const int chunk = tid + i * 256;       // 2048 chunks of 16B
        const int row = chunk >> 4;
        const int o = chunk & 15;
        uint32_t r0, r1, r2, r3;
        asm volatile("ld.shared.v4.b32 {%0,%1,%2,%3}, [%4];"
            : "=r"(r0), "=r"(r1), "=r"(r2), "=r"(r3)
            : "r"(se + (uint32_t)((row * EROWS + o * 4) << 2)));
        uint4 v = make_uint4(r0, r1, r2, r3);
        *(uint4*)(C2 + (size_t)(rowBase + row) * Hh + (colBase >> 1) + o * 4) = v;
    }
}

// ===========================================================================
// Scan over half2 (c, v) pairs: h_t = c_t * h_{t-1} + v_t   (fp32 state)
// ===========================================================================
__global__ __launch_bounds__(256) void scan_carry1_kernel(const __half2* __restrict__ gh)
{
    const int g = blockIdx.x * blockDim.x + threadIdx.x;
    const int h = g & (Hh - 1);
    const int rest = g >> 9;
    const int b = rest & (Bb - 1);
    const int k = rest >> 3;

    const __half2* p = gh + ((size_t)(b * Ss + k * CLEN) * Hh + h);
    float P = 1.0f, hl = 0.0f;
#pragma unroll 8
    for (int i = 0; i < CLEN; i++) {
        float2 cv = __half22float2(*p);
        hl = fmaf(cv.x, hl, cv.y);
        P *= cv.x;
        p += Hh;
    }
    const int ch = b * Hh + h;
    g_carryP[k * NCH + ch] = P;
    g_carryH[k * NCH + ch] = hl;
}

__global__ __launch_bounds__(256) void scan_carry_kernel(float* __restrict__ nh_out)
{
    const int ch = blockIdx.x * blockDim.x + threadIdx.x;
    float hcur = 0.5f;
#pragma unroll 4
    for (int k = 0; k < NCHUNK; k++) {
        g_entry[k * NCH + ch] = hcur;
        hcur = fmaf(g_carryP[k * NCH + ch], hcur, g_carryH[k * NCH + ch]);
    }
    nh_out[ch] = hcur;
}

// Pass 3, layer-1: write final fp32 output
__global__ __launch_bounds__(256) void scan_emit_f32_kernel(
    const __half2* __restrict__ gh, float* __restrict__ outbuf)
{
    const int g = blockIdx.x * blockDim.x + threadIdx.x;
    const int h = g & (Hh - 1);
    const int rest = g >> 9;
    const int b = rest & (Bb - 1);
    const int k = rest >> 3;

    float hv = g_entry[k * NCH + b * Hh + h];
    const __half2* p = gh + ((size_t)(b * Ss + k * CLEN) * Hh + h);
    size_t obase = ((size_t)(b * Ss + k * CLEN)) * Hh + h;
#pragma unroll 8
    for (int i = 0; i < CLEN; i++) {
        float2 cv = __half22float2(*p);
        hv = fmaf(cv.x, hv, cv.y);
        outbuf[obase] = hv;
        p += Hh;
        obase += Hh;
    }
}

// Pass 3, layer-0: write fp16 A operand for layer 1
__global__ __launch_bounds__(256) void scan_emit_f16_kernel(
    const __half2* __restrict__ gh, __half* __restrict__ outA)
{
    const int g = blockIdx.x * blockDim.x + threadIdx.x;
    const int h = g & (Hh - 1);
    const int rest = g >> 9;
    const int b = rest & (Bb - 1);
    const int k = rest >> 3;

    float hv = g_entry[k * NCH + b * Hh + h];
    const __half2* p = gh + ((size_t)(b * Ss + k * CLEN) * Hh + h);
    size_t obase = ((size_t)(b * Ss + k * CLEN)) * Hh + h;
#pragma unroll 8
    for (int i = 0; i < CLEN; i++) {
        float2 cv = __half22float2(*p);
        hv = fmaf(cv.x, hv, cv.y);
        outA[obase] = __float2half_rn(hv);
        p += Hh;
        obase += Hh;
    }
}

// ===========================================================================
extern "C" void kernel_launch(void* const* d_in, const int* in_sizes, int n_in,
                              void* d_out, int out_size)
{
    const float* x  = (const float*)d_in[0];
    const float* w0 = (const float*)d_in[1];
    const float* b0 = (const float*)d_in[2];
    const float* w1 = (const float*)d_in[3];
    const float* b1 = (const float*)d_in[4];
    float* out = (float*)d_out;

    __half* gh;  cudaGetSymbolAddress((void**)&gh,  g_gh);
    __half* Ax;  cudaGetSymbolAddress((void**)&Ax,  g_Ax);
    __half* A1;  cudaGetSymbolAddress((void**)&A1,  g_A1);
    __half* Wb0; cudaGetSymbolAddress((void**)&Wb0, g_Wb0);
    __half* Wb1; cudaGetSymbolAddress((void**)&Wb1, g_Wb1);

    float* nh0 = out + (size_t)Mm * Hh;
    float* nh1 = nh0 + (size_t)Bb * Hh;

    cudaFuncSetAttribute(hmma_gemm_act,
                         cudaFuncAttributeMaxDynamicSharedMemorySize, GEMM_SMEM);

    dim3 ggrid(GH / BN, Mm / BM);                  // (8, 256)
    const int scan_blocks = (NCHUNK * NCH) / 256;  // 1024

    // One-time conversions (cheap)
    conv_b_kernel<<<(GH * 128) / 256, 256>>>(w0, Wb0);
    conv_b_kernel<<<(GH * 128) / 256, 256>>>(w1, Wb1);
    conv_a_kernel<<<(Mm * 128) / 256, 256>>>(x, Ax);

    // ---- Layer 0 ----
    hmma_gemm_act<<<ggrid, 256, GEMM_SMEM>>>(Ax, Wb0, b0, (__half2*)gh);
    scan_carry1_kernel<<<scan_blocks, 256>>>((const __half2*)gh);
    scan_carry_kernel<<<NCH / 256, 256>>>(nh0);
    scan_emit_f16_kernel<<<scan_blocks, 256>>>((const __half2*)gh, A1);

    // ---- Layer 1 ----
    hmma_gemm_act<<<ggrid, 256, GEMM_SMEM>>>(A1, Wb1, b1, (__half2*)gh);
    scan_carry1_kernel<<<scan_blocks, 256>>>((const __half2*)gh);
    scan_carry_kernel<<<NCH / 256, 256>>>(nh1);
    scan_emit_f32_kernel<<<scan_blocks, 256>>>((const __half2*)gh, out);
}